// round 15
// baseline (speedup 1.0000x reference)
#include <cuda_runtime.h>
#include <cuda_bf16.h>
#include <cuda_fp16.h>
#include <math.h>
#include <stdint.h>

#define NN   20000
#define NE   160000
#define NPAD 20096
#define HID  128
#define HEADS 8
#define HC   1024
#define LAYERS 6

// ---------------- scratch (device globals; no allocation allowed) ----------
static __device__ float g_h  [NN * HID];
static __device__ float g_hn [NN * HID];
static __device__ __align__(16) __half g_hh_hi[NPAD * HID];  // split h (fp16 hi/lo)
static __device__ __align__(16) __half g_hh_lo[NPAD * HID];
static __device__ __align__(16) __half g_qh[NN * HC];   // q in fp16
static __device__ __align__(16) __half g_kh[NN * HC];   // k in fp16
static __device__ __align__(16) __half g_vh[NN * HC];   // v in fp16
static __device__ __align__(16) __half g_xrh[NN * HC];  // xr in fp16
static __device__ __align__(16) __half g_oh[NPAD * HC]; // split attn out (fp16 hi/lo)
static __device__ __align__(16) __half g_ol[NPAD * HC];
// CSR
static __device__ int g_deg   [NN];
static __device__ int g_rowptr[NN + 1];
static __device__ int g_cur   [NN];
static __device__ int g_esrc  [NE];
// split-fp16 weights: qkvs transposed [z=l*4+ws][n=1024][k=128], proj [l][n=128][k=1024]
static __device__ __align__(16) __half g_wA_hi[LAYERS * 4 * 1024 * 128];
static __device__ __align__(16) __half g_wA_lo[LAYERS * 4 * 1024 * 128];
static __device__ __align__(16) __half g_wP_hi[LAYERS * 128 * 1024];
static __device__ __align__(16) __half g_wP_lo[LAYERS * 128 * 1024];
// beta-gate effective weights: w_a = Wb1 + Wb3, w_b = Wb2 - Wb3
static __device__ float g_wba[LAYERS * HC];
static __device__ float g_wbb[LAYERS * HC];

// ==================== PTX helpers ============================================
__device__ __forceinline__ uint32_t smem_u32(const void* p) {
    uint32_t a;
    asm("{ .reg .u64 t; cvta.to.shared.u64 t, %1; cvt.u32.u64 %0, t; }" : "=r"(a) : "l"(p));
    return a;
}
__device__ __forceinline__ void ldsm4(uint32_t& r0, uint32_t& r1, uint32_t& r2, uint32_t& r3,
                                      uint32_t addr) {
    asm volatile("ldmatrix.sync.aligned.m8n8.x4.shared.b16 {%0,%1,%2,%3}, [%4];"
                 : "=r"(r0), "=r"(r1), "=r"(r2), "=r"(r3) : "r"(addr));
}
// main term: fp16 x fp16 -> fp32 accum
__device__ __forceinline__ void mma_f32(float* c, const uint32_t* a, uint32_t b0, uint32_t b1) {
    asm volatile("mma.sync.aligned.m16n8k16.row.col.f32.f16.f16.f32 "
                 "{%0,%1,%2,%3}, {%4,%5,%6,%7}, {%8,%9}, {%0,%1,%2,%3};"
                 : "+f"(c[0]), "+f"(c[1]), "+f"(c[2]), "+f"(c[3])
                 : "r"(a[0]), "r"(a[1]), "r"(a[2]), "r"(a[3]), "r"(b0), "r"(b1));
}
// cross terms: fp16 x fp16 -> fp16 accum (c = 2 regs of f16x2)
__device__ __forceinline__ void mma_f16(uint32_t* c, const uint32_t* a, uint32_t b0, uint32_t b1) {
    asm volatile("mma.sync.aligned.m16n8k16.row.col.f16.f16.f16.f16 "
                 "{%0,%1}, {%2,%3,%4,%5}, {%6,%7}, {%0,%1};"
                 : "+r"(c[0]), "+r"(c[1])
                 : "r"(a[0]), "r"(a[1]), "r"(a[2]), "r"(a[3]), "r"(b0), "r"(b1));
}
__device__ __forceinline__ void cp_async16(uint32_t dst, const void* src) {
    asm volatile("cp.async.cg.shared.global [%0], [%1], 16;" :: "r"(dst), "l"(src) : "memory");
}
#define CP_COMMIT() asm volatile("cp.async.commit_group;" ::: "memory")
#define CP_WAIT0()  asm volatile("cp.async.wait_group 0;" ::: "memory")

__device__ __forceinline__ uint32_t pack_h2(float x, float y) {
    __half2 t = __floats2half2_rn(x, y);
    return *(uint32_t*)&t;
}
// fp16 hi/lo split: hi = rn(x), lo = rn(x - hi); residual ~2^-22|x|
__device__ __forceinline__ void split2(float a, float b, uint32_t& hi, uint32_t& lo) {
    __half h0 = __float2half_rn(a), h1 = __float2half_rn(b);
    float l0 = a - __half2float(h0), l1 = b - __half2float(h1);
    __half2 th(h0, h1);
    hi = *(uint32_t*)&th;
    lo = pack_h2(l0, l1);
}
__device__ __forceinline__ void unpack8(uint4 u, float* f) {
    float2 a = __half22float2(*(__half2*)&u.x);
    float2 b = __half22float2(*(__half2*)&u.y);
    float2 c = __half22float2(*(__half2*)&u.z);
    float2 d = __half22float2(*(__half2*)&u.w);
    f[0]=a.x; f[1]=a.y; f[2]=b.x; f[3]=b.y; f[4]=c.x; f[5]=c.y; f[6]=d.x; f[7]=d.y;
}

// tile row: 512B = 32 chunks of 16B; hi chunks 0-15, lo 16-31
__device__ __forceinline__ uint32_t sw_off(int r, int chunk) {
    return (uint32_t)(r * 512 + ((chunk ^ (r & 7)) << 4));
}

// qkvs smem layout (M128): A 64KB, B0/B1 64KB each
#define SA_OFF  0
#define SB0_OFF 65536
#define SB1_OFF 131072
#define MMASMEM 196608
// proj smem layout (M64): A 32KB, B0/B1 64KB each
#define PA_OFF  0
#define PB0_OFF 32768
#define PB1_OFF 98304
#define PROJSMEM 163840

// ---------------- MMA mainloop, 128x128 tile (8 warps 4x2) ------------------
// accf: f32 hi*hi accum; acch: f16 accum for cross terms (2 f16x2 regs per frag)
__device__ __forceinline__ void mma_k128(uint32_t smA, uint32_t smB, int lane,
                                         int wm, int wn,
                                         float accf[2][8][4], uint32_t acch[2][8][2]) {
    int arow0 = wm * 32 + (lane & 15);
    int asel  = (lane >> 4) & 1;
    int brow0 = wn * 64 + (lane & 7) + ((lane >> 4) & 1) * 8;
    int bsel  = (lane >> 3) & 1;
    #pragma unroll
    for (int k16 = 0; k16 < 8; k16++) {
        int ch = 2 * k16;
        uint32_t ah[2][4], al[2][4];
        #pragma unroll
        for (int mf = 0; mf < 2; mf++) {
            int r = arow0 + mf * 16;
            uint32_t ad = smA + sw_off(r, ch + asel);
            ldsm4(ah[mf][0], ah[mf][1], ah[mf][2], ah[mf][3], ad);
            ldsm4(al[mf][0], al[mf][1], al[mf][2], al[mf][3], ad + 256);
        }
        uint32_t bh_[8][2], bl_[8][2];
        #pragma unroll
        for (int p = 0; p < 4; p++) {
            int r = brow0 + p * 16;
            uint32_t bd = smB + sw_off(r, ch + bsel);
            ldsm4(bh_[2*p][0], bh_[2*p][1], bh_[2*p+1][0], bh_[2*p+1][1], bd);
            ldsm4(bl_[2*p][0], bl_[2*p][1], bl_[2*p+1][0], bl_[2*p+1][1], bd + 256);
        }
        #pragma unroll
        for (int mf = 0; mf < 2; mf++)
            #pragma unroll
            for (int nf = 0; nf < 8; nf++) {
                mma_f32(accf[mf][nf], ah[mf], bh_[nf][0], bh_[nf][1]);
                mma_f16(acch[mf][nf], al[mf], bh_[nf][0], bh_[nf][1]);
                mma_f16(acch[mf][nf], ah[mf], bl_[nf][0], bl_[nf][1]);
            }
    }
}

// ---------------- MMA mainloop, 64x128 tile (8 warps 2x4) -------------------
__device__ __forceinline__ void mma_k128_m64(uint32_t smA, uint32_t smB, int lane,
                                             int wm, int wn,
                                             float accf[2][4][4], uint32_t acch[2][4][2]) {
    int arow0 = wm * 32 + (lane & 15);
    int asel  = (lane >> 4) & 1;
    int brow0 = wn * 32 + (lane & 7) + ((lane >> 4) & 1) * 8;
    int bsel  = (lane >> 3) & 1;
    #pragma unroll
    for (int k16 = 0; k16 < 8; k16++) {
        int ch = 2 * k16;
        uint32_t ah[2][4], al[2][4];
        #pragma unroll
        for (int mf = 0; mf < 2; mf++) {
            int r = arow0 + mf * 16;
            uint32_t ad = smA + sw_off(r, ch + asel);
            ldsm4(ah[mf][0], ah[mf][1], ah[mf][2], ah[mf][3], ad);
            ldsm4(al[mf][0], al[mf][1], al[mf][2], al[mf][3], ad + 256);
        }
        uint32_t bh_[4][2], bl_[4][2];
        #pragma unroll
        for (int p = 0; p < 2; p++) {
            int r = brow0 + p * 16;
            uint32_t bd = smB + sw_off(r, ch + bsel);
            ldsm4(bh_[2*p][0], bh_[2*p][1], bh_[2*p+1][0], bh_[2*p+1][1], bd);
            ldsm4(bl_[2*p][0], bl_[2*p][1], bl_[2*p+1][0], bl_[2*p+1][1], bd + 256);
        }
        #pragma unroll
        for (int mf = 0; mf < 2; mf++)
            #pragma unroll
            for (int nf = 0; nf < 4; nf++) {
                mma_f32(accf[mf][nf], ah[mf], bh_[nf][0], bh_[nf][1]);
                mma_f16(acch[mf][nf], al[mf], bh_[nf][0], bh_[nf][1]);
                mma_f16(acch[mf][nf], ah[mf], bl_[nf][0], bl_[nf][1]);
            }
    }
}

// ---------------- qkvs GEMM: M128 tiles, pure cp.async staging ---------------
// grid (8, 157): x = ws*2 + nhalf, y = m-tile(128). All outputs fp16.
__global__ __launch_bounds__(256, 1) void gemm_qkvs_mma(
        const float* __restrict__ bq, const float* __restrict__ bk,
        const float* __restrict__ bv, const float* __restrict__ bs,
        int l, int M) {
    extern __shared__ char sm[];
    int tid = threadIdx.x, wid = tid >> 5, lane = tid & 31;
    int ws = blockIdx.x >> 1, nh = blockIdx.x & 1;
    int m0 = blockIdx.y * 128;
    int z = l * 4 + ws;
    const float* bias = ws == 0 ? bq : ws == 1 ? bk : ws == 2 ? bv : bs;
    __half* Ch = ws == 0 ? g_qh : ws == 1 ? g_kh : ws == 2 ? g_vh : g_xrh;
    const uint4* bhp = (const uint4*)g_wA_hi + (size_t)z * 1024 * 16;
    const uint4* blp = (const uint4*)g_wA_lo + (size_t)z * 1024 * 16;
    uint32_t smb = smem_u32(sm);

    // prefetch A (pre-split) and B tile 0, all async
    for (int i = tid; i < 2048; i += 256) {
        int r = i >> 4, c = i & 15;
        uint32_t oa = smb + SA_OFF + sw_off(r, c);
        cp_async16(oa,       g_hh_hi + (size_t)(m0 + r) * 128 + c * 8);
        cp_async16(oa + 256, g_hh_lo + (size_t)(m0 + r) * 128 + c * 8);
        int n0 = nh * 512;
        uint32_t ob = smb + SB0_OFF + sw_off(r, c);
        cp_async16(ob,       bhp + (size_t)(n0 + r) * 16 + c);
        cp_async16(ob + 256, blp + (size_t)(n0 + r) * 16 + c);
    }
    CP_COMMIT();
    CP_WAIT0();
    __syncthreads();

    int wm = wid >> 1, wn = wid & 1;
    for (int nt = 0; nt < 4; nt++) {
        int n0 = (nh * 4 + nt) * 128;
        if (nt < 3) {      // prefetch next B tile into the other buffer
            int n1 = n0 + 128;
            uint32_t boff = ((nt + 1) & 1) ? SB1_OFF : SB0_OFF;
            for (int i = tid; i < 2048; i += 256) {
                int r = i >> 4, c = i & 15;
                uint32_t oh = smb + boff + sw_off(r, c);
                cp_async16(oh,       bhp + (size_t)(n1 + r) * 16 + c);
                cp_async16(oh + 256, blp + (size_t)(n1 + r) * 16 + c);
            }
            CP_COMMIT();
        }
        float acc[2][8][4] = {};
        uint32_t acch[2][8][2] = {};
        mma_k128(smb + SA_OFF, smb + ((nt & 1) ? SB1_OFF : SB0_OFF), lane, wm, wn, acc, acch);

        int colb = n0 + wn * 64 + (lane & 3) * 2;
        #pragma unroll
        for (int mf = 0; mf < 2; mf++) {
            int r0 = m0 + wm * 32 + mf * 16 + (lane >> 2);
            #pragma unroll
            for (int nf = 0; nf < 8; nf++) {
                int col = colb + nf * 8;
                float2 bb = *(const float2*)(bias + col);
                float2 e0 = __half22float2(*(__half2*)&acch[mf][nf][0]);
                float2 e1 = __half22float2(*(__half2*)&acch[mf][nf][1]);
                if (r0 < M)
                    *(uint32_t*)(Ch + (size_t)r0 * HC + col) =
                        pack_h2(acc[mf][nf][0] + e0.x + bb.x, acc[mf][nf][1] + e0.y + bb.y);
                if (r0 + 8 < M)
                    *(uint32_t*)(Ch + (size_t)(r0 + 8) * HC + col) =
                        pack_h2(acc[mf][nf][2] + e1.x + bb.x, acc[mf][nf][3] + e1.y + bb.y);
            }
        }
        if (nt < 3) CP_WAIT0();
        __syncthreads();
    }
}

// ---------------- proj GEMM: M64 tiles (313 blocks) -------------------------
// grid (1, 313). 8 warps = 2(m) x 4(n), each 32x32.
// Epilogue writes fp32 C (+resid+relu) AND split h for next qkvs.
__global__ __launch_bounds__(256, 1) void gemm_proj_mma(
        const float* __restrict__ bias, const float* __restrict__ resid,
        float* __restrict__ C, int l, int M) {
    extern __shared__ char sm[];
    int tid = threadIdx.x, wid = tid >> 5, lane = tid & 31;
    int m0 = blockIdx.y * 64;
    const uint4* ahp = (const uint4*)g_oh + (size_t)m0 * 128;          // [row][128 u4]
    const uint4* alp = (const uint4*)g_ol + (size_t)m0 * 128;
    const uint4* bhp = (const uint4*)g_wP_hi + (size_t)l * 128 * 128;  // [n=128][128 u4]
    const uint4* blp = (const uint4*)g_wP_lo + (size_t)l * 128 * 128;
    uint32_t smb = smem_u32(sm);

    // prefetch A chunk 0 (64 rows) + B chunk 0 (128 rows)
    for (int i = tid; i < 1024; i += 256) {
        int r = i >> 4, c = i & 15;
        uint32_t oa = smb + PA_OFF + sw_off(r, c);
        cp_async16(oa,       ahp + (size_t)r * 128 + c);
        cp_async16(oa + 256, alp + (size_t)r * 128 + c);
    }
    for (int i = tid; i < 2048; i += 256) {
        int r = i >> 4, c = i & 15;
        uint32_t ob = smb + PB0_OFF + sw_off(r, c);
        cp_async16(ob,       bhp + (size_t)r * 128 + c);
        cp_async16(ob + 256, blp + (size_t)r * 128 + c);
    }
    CP_COMMIT();
    CP_WAIT0();
    __syncthreads();

    float acc[2][4][4] = {};
    uint32_t acch[2][4][2] = {};
    int wm = wid >> 2, wn = wid & 3;

    for (int ck = 0; ck < 8; ck++) {
        if (ck < 7) {     // prefetch next B chunk (overlaps MMA)
            uint32_t boff = ((ck + 1) & 1) ? PB1_OFF : PB0_OFF;
            for (int i = tid; i < 2048; i += 256) {
                int r = i >> 4, c = i & 15;
                uint32_t oh = smb + boff + sw_off(r, c);
                cp_async16(oh,       bhp + (size_t)r * 128 + (ck + 1) * 16 + c);
                cp_async16(oh + 256, blp + (size_t)r * 128 + (ck + 1) * 16 + c);
            }
            CP_COMMIT();
        }
        mma_k128_m64(smb + PA_OFF, smb + ((ck & 1) ? PB1_OFF : PB0_OFF),
                     lane, wm, wn, acc, acch);
        __syncthreads();
        if (ck < 7) {     // restage A for next chunk (pure async copy, 32KB)
            for (int i = tid; i < 1024; i += 256) {
                int r = i >> 4, c = i & 15;
                uint32_t oa = smb + PA_OFF + sw_off(r, c);
                cp_async16(oa,       ahp + (size_t)r * 128 + (ck + 1) * 16 + c);
                cp_async16(oa + 256, alp + (size_t)r * 128 + (ck + 1) * 16 + c);
            }
            CP_COMMIT();
            CP_WAIT0();
        }
        __syncthreads();
    }

    int colb = wn * 32 + (lane & 3) * 2;
    #pragma unroll
    for (int mf = 0; mf < 2; mf++) {
        int r0 = m0 + wm * 32 + mf * 16 + (lane >> 2);
        #pragma unroll
        for (int nf = 0; nf < 4; nf++) {
            int col = colb + nf * 8;
            float2 bb = *(const float2*)(bias + col);
            float2 e0 = __half22float2(*(__half2*)&acch[mf][nf][0]);
            float2 e1 = __half22float2(*(__half2*)&acch[mf][nf][1]);
            if (r0 < M) {
                float2 rr = *(const float2*)(resid + (size_t)r0 * HID + col);
                float2 o;
                o.x = fmaxf(acc[mf][nf][0] + e0.x + bb.x + rr.x, 0.f);
                o.y = fmaxf(acc[mf][nf][1] + e0.y + bb.y + rr.y, 0.f);
                *(float2*)(C + (size_t)r0 * HID + col) = o;
                uint32_t hp, lp;
                split2(o.x, o.y, hp, lp);
                *(uint32_t*)(g_hh_hi + (size_t)r0 * HID + col) = hp;
                *(uint32_t*)(g_hh_lo + (size_t)r0 * HID + col) = lp;
            }
            if (r0 + 8 < M) {
                float2 rr = *(const float2*)(resid + (size_t)(r0 + 8) * HID + col);
                float2 o;
                o.x = fmaxf(acc[mf][nf][2] + e1.x + bb.x + rr.x, 0.f);
                o.y = fmaxf(acc[mf][nf][3] + e1.y + bb.y + rr.y, 0.f);
                *(float2*)(C + (size_t)(r0 + 8) * HID + col) = o;
                uint32_t hp, lp;
                split2(o.x, o.y, hp, lp);
                *(uint32_t*)(g_hh_hi + (size_t)(r0 + 8) * HID + col) = hp;
                *(uint32_t*)(g_hh_lo + (size_t)(r0 + 8) * HID + col) = lp;
            }
        }
    }
}

// ---------------- weight transpose + split (fp16 hi/lo) ----------------------
__global__ void tsplit_qkvs(const float* __restrict__ Wq, const float* __restrict__ Wk,
                            const float* __restrict__ Wv, const float* __restrict__ Ws) {
    __shared__ float t[32][33];
    int z = blockIdx.z, l = z >> 2, ws = z & 3;
    const float* W = (ws == 0 ? Wq : ws == 1 ? Wk : ws == 2 ? Wv : Ws) + (size_t)l * 128 * HC;
    __half* oh = g_wA_hi + (size_t)z * 1024 * 128;
    __half* ol = g_wA_lo + (size_t)z * 1024 * 128;
    int n0 = blockIdx.x * 32, k0 = blockIdx.y * 32;
    int tx = threadIdx.x, ty = threadIdx.y;
    #pragma unroll
    for (int i = 0; i < 4; i++)
        t[ty + 8 * i][tx] = W[(size_t)(k0 + ty + 8 * i) * HC + n0 + tx];
    __syncthreads();
    #pragma unroll
    for (int i = 0; i < 4; i++) {
        float v = t[tx][ty + 8 * i];
        __half h = __float2half_rn(v);
        size_t o = (size_t)(n0 + ty + 8 * i) * 128 + k0 + tx;
        oh[o] = h;
        ol[o] = __float2half_rn(v - __half2float(h));
    }
}
__global__ void tsplit_proj(const float* __restrict__ Wp) {
    __shared__ float t[32][33];
    int l = blockIdx.z;
    const float* W = Wp + (size_t)l * 1024 * 128;
    __half* oh = g_wP_hi + (size_t)l * 128 * 1024;
    __half* ol = g_wP_lo + (size_t)l * 128 * 1024;
    int n0 = blockIdx.x * 32, k0 = blockIdx.y * 32;
    int tx = threadIdx.x, ty = threadIdx.y;
    #pragma unroll
    for (int i = 0; i < 4; i++)
        t[ty + 8 * i][tx] = W[(size_t)(k0 + ty + 8 * i) * 128 + n0 + tx];
    __syncthreads();
    #pragma unroll
    for (int i = 0; i < 4; i++) {
        float v = t[tx][ty + 8 * i];
        __half h = __float2half_rn(v);
        size_t o = (size_t)(n0 + ty + 8 * i) * 1024 + k0 + tx;
        oh[o] = h;
        ol[o] = __float2half_rn(v - __half2float(h));
    }
}
// beta-gate effective weights
__global__ void weff_kernel(const float* __restrict__ Wb) {
    int i = blockIdx.x * blockDim.x + threadIdx.x;
    if (i < LAYERS * HC) {
        int l = i / HC, c = i % HC;
        const float* w = Wb + (size_t)l * 3 * HC;
        g_wba[i] = w[c] + w[2 * HC + c];
        g_wbb[i] = w[HC + c] - w[2 * HC + c];
    }
}

// ---------------- input projection: 16 nodes/block, Win cached in smem ------
__global__ __launch_bounds__(128) void inproj_kernel(
        const float* __restrict__ x, const float* __restrict__ Win,
        const float* __restrict__ b_in, float* __restrict__ h) {
    __shared__ float sw[15][128];
    __shared__ float sb[128];
    __shared__ float sx[16][16];
    int j = threadIdx.x;
    #pragma unroll
    for (int k = 0; k < 15; k++) sw[k][j] = Win[k * HID + j];
    sb[j] = b_in[j];
    int nb = blockIdx.x * 16;
    for (int i = j; i < 240; i += 128) {
        int ni = i / 15, ci = i % 15;
        int n = nb + ni;
        sx[ni][ci] = (n < NN) ? x[(size_t)n * 15 + ci] : 0.f;
    }
    __syncthreads();
    #pragma unroll 4
    for (int ni = 0; ni < 16; ni++) {
        int n = nb + ni;
        if (n >= NN) break;
        float acc = sb[j];
        #pragma unroll
        for (int k = 0; k < 15; k++) acc += sx[ni][k] * sw[k][j];
        h[(size_t)n * HID + j] = acc;
        __half hi = __float2half_rn(acc);
        g_hh_hi[(size_t)n * HID + j] = hi;
        g_hh_lo[(size_t)n * HID + j] = __float2half_rn(acc - __half2float(hi));
    }
}

// ---------------- CSR build --------------------------------------------------
__global__ void csr_zero() {
    int i = blockIdx.x * blockDim.x + threadIdx.x;
    if (i < NN) g_deg[i] = 0;
}
__global__ void csr_count(const int* __restrict__ ei) {
    int e = blockIdx.x * blockDim.x + threadIdx.x;
    if (e < NE) atomicAdd(&g_deg[ei[NE + e]], 1);
}
__global__ __launch_bounds__(1024) void csr_scan() {
    __shared__ int wsum[32], wofs[32], s_tot;
    int t = threadIdx.x, lane = t & 31, w = t >> 5;
    int base = 0;
    for (int i0 = 0; i0 < NN; i0 += 1024) {
        int i = i0 + t;
        int v = (i < NN) ? g_deg[i] : 0;
        int s = v;
        #pragma unroll
        for (int o = 1; o < 32; o <<= 1) {
            int u = __shfl_up_sync(0xffffffffu, s, o);
            if (lane >= o) s += u;
        }
        if (lane == 31) wsum[w] = s;
        __syncthreads();
        if (w == 0) {
            int a = wsum[lane];
            int ss = a;
            #pragma unroll
            for (int o = 1; o < 32; o <<= 1) {
                int u = __shfl_up_sync(0xffffffffu, ss, o);
                if (lane >= o) ss += u;
            }
            wofs[lane] = ss - a;
            if (lane == 31) s_tot = ss;
        }
        __syncthreads();
        int excl = base + wofs[w] + (s - v);
        if (i < NN) { g_rowptr[i] = excl; g_cur[i] = excl; }
        base += s_tot;
        __syncthreads();
    }
    if (t == 0) g_rowptr[NN] = base;
}
__global__ void csr_fill(const int* __restrict__ ei) {
    int e = blockIdx.x * blockDim.x + threadIdx.x;
    if (e < NE) {
        int dst = ei[NE + e];
        int pos = atomicAdd(&g_cur[dst], 1);
        g_esrc[pos] = ei[e];
    }
}

// ---------------- fused attention + beta gate + LayerNorm -------------------
// block = 128 threads; thread t: head h = t>>4, owns 8 cols. No-max softmax,
// 2-way unrolled edge streams. Single-pass LN (Var = E[g^2] - mu^2).
__device__ __forceinline__ float breduce128(float v, float* red) {
    #pragma unroll
    for (int o = 16; o; o >>= 1) v += __shfl_xor_sync(0xffffffffu, v, o);
    if ((threadIdx.x & 31) == 0) red[threadIdx.x >> 5] = v;
    __syncthreads();
    float r = red[0] + red[1] + red[2] + red[3];
    __syncthreads();
    return r;
}
__device__ __forceinline__ float2 breduce128_2(float a, float b, float* red) {
    #pragma unroll
    for (int o = 16; o; o >>= 1) {
        a += __shfl_xor_sync(0xffffffffu, a, o);
        b += __shfl_xor_sync(0xffffffffu, b, o);
    }
    if ((threadIdx.x & 31) == 0) {
        red[(threadIdx.x >> 5) * 2]     = a;
        red[(threadIdx.x >> 5) * 2 + 1] = b;
    }
    __syncthreads();
    float2 r;
    r.x = red[0] + red[2] + red[4] + red[6];
    r.y = red[1] + red[3] + red[5] + red[7];
    __syncthreads();
    return r;
}

__global__ __launch_bounds__(128) void attn_fused(
        const float* __restrict__ wba, const float* __restrict__ wbb,
        const float* __restrict__ lng, const float* __restrict__ lnb) {
    int n = blockIdx.x;
    int t = threadIdx.x;
    int off = (t >> 4) * 128 + (t & 15) * 8;
    __shared__ float red[8];
    const float RSQ = 0.08838834764831845f;   // 1/sqrt(128)

    float q[8];
    unpack8(*(const uint4*)(g_qh + (size_t)n * HC + off), q);

    float acc0[8] = {}, acc1[8] = {};
    float d0 = 0.f, d1 = 0.f;

    int beg = g_rowptr[n], end = g_rowptr[n + 1];
    int p = beg;
    for (; p + 1 < end; p += 2) {
        int s0 = g_esrc[p], s1 = g_esrc[p + 1];
        uint4 ku0 = *(const uint4*)(g_kh + (size_t)s0 * HC + off);
        uint4 ku1 = *(const uint4*)(g_kh + (size_t)s1 * HC + off);
        uint4 vu0 = *(const uint4*)(g_vh + (size_t)s0 * HC + off);
        uint4 vu1 = *(const uint4*)(g_vh + (size_t)s1 * HC + off);
        float k0[8], k1[8], v0[8], v1[8];
        unpack8(ku0, k0); unpack8(ku1, k1);
        unpack8(vu0, v0); unpack8(vu1, v1);
        float dot0 = 0.f, dot1 = 0.f;
        #pragma unroll
        for (int i = 0; i < 8; i++) { dot0 += q[i] * k0[i]; dot1 += q[i] * k1[i]; }
        #pragma unroll
        for (int o = 8; o; o >>= 1) {
            dot0 += __shfl_xor_sync(0xffffffffu, dot0, o);
            dot1 += __shfl_xor_sync(0xffffffffu, dot1, o);
        }
        float pw0 = __expf(dot0 * RSQ);
        float pw1 = __expf(dot1 * RSQ);
        d0 += pw0; d1 += pw1;
        #pragma unroll
        for (int i = 0; i < 8; i++) {
            acc0[i] += pw0 * v0[i];
            acc1[i] += pw1 * v1[i];
        }
    }
    if (p < end) {
        int s0 = g_esrc[p];
        uint4 ku0 = *(const uint4*)(g_kh + (size_t)s0 * HC + off);
        uint4 vu0 = *(const uint4*)(g_vh + (size_t)s0 * HC + off);
        float k0[8], v0[8];
        unpack8(ku0, k0); unpack8(vu0, v0);
        float dot0 = 0.f;
        #pragma unroll
        for (int i = 0; i < 8; i++) dot0 += q[i] * k0[i];
        #pragma unroll
        for (int o = 8; o; o >>= 1) dot0 += __shfl_xor_sync(0xffffffffu, dot0, o);
        float pw0 = __expf(dot0 * RSQ);
        d0 += pw0;
        #pragma unroll
        for (int i = 0; i < 8; i++) acc0[i] += pw0 * v0[i];
    }

    float inv = 1.f / (d0 + d1 + 1e-16f);
    float outv[8];
    #pragma unroll
    for (int i = 0; i < 8; i++) outv[i] = (acc0[i] + acc1[i]) * inv;

    float xr[8];
    unpack8(*(const uint4*)(g_xrh + (size_t)n * HC + off), xr);
    float bsum = 0.f;
    #pragma unroll
    for (int i = 0; i < 8; i++)
        bsum += outv[i] * wba[off + i] + xr[i] * wbb[off + i];
    float tot = breduce128(bsum, red);
    float beta = 1.f / (1.f + __expf(-tot));

    float g[8], gsum = 0.f, g2sum = 0.f;
    #pragma unroll
    for (int i = 0; i < 8; i++) {
        g[i] = beta * xr[i] + (1.f - beta) * outv[i];
        gsum += g[i];
        g2sum += g[i] * g[i];
    }
    float2 ms = breduce128_2(gsum, g2sum, red);
    float mu  = ms.x * (1.f / HC);
    float var = ms.y * (1.f / HC) - mu * mu;
    float rstd = rsqrtf(var + 1e-5f);

    const float4* lg = (const float4*)(lng + off);
    const float4* lb = (const float4*)(lnb + off);
    float4 lg0 = lg[0], lg1 = lg[1], lb0 = lb[0], lb1 = lb[1];
    float gl[8] = {lg0.x, lg0.y, lg0.z, lg0.w, lg1.x, lg1.y, lg1.z, lg1.w};
    float bl[8] = {lb0.x, lb0.y, lb0.z, lb0.w, lb1.x, lb1.y, lb1.z, lb1.w};
    float o[8];
    #pragma unroll
    for (int i = 0; i < 8; i++) o[i] = (g[i] - mu) * rstd * gl[i] + bl[i];

    uint4 hu, lu;
    split2(o[0], o[1], hu.x, lu.x);
    split2(o[2], o[3], hu.y, lu.y);
    split2(o[4], o[5], hu.z, lu.z);
    split2(o[6], o[7], hu.w, lu.w);
    *(uint4*)(g_oh + (size_t)n * HC + off) = hu;
    *(uint4*)(g_ol + (size_t)n * HC + off) = lu;
}

// ---------------- launch -----------------------------------------------------
extern "C" void kernel_launch(void* const* d_in, const int* in_sizes, int n_in,
                              void* d_out, int out_size) {
    const float* x    = (const float*)d_in[0];
    const int*   ei   = (const int*)  d_in[1];
    const float* Win  = (const float*)d_in[2];
    const float* b_in = (const float*)d_in[3];
    const float* Wq   = (const float*)d_in[4];
    const float* bq   = (const float*)d_in[5];
    const float* Wk   = (const float*)d_in[6];
    const float* bk   = (const float*)d_in[7];
    const float* Wv   = (const float*)d_in[8];
    const float* bv   = (const float*)d_in[9];
    const float* Ws   = (const float*)d_in[10];
    const float* bs   = (const float*)d_in[11];
    const float* Wb   = (const float*)d_in[12];
    const float* lng  = (const float*)d_in[13];
    const float* lnb  = (const float*)d_in[14];
    const float* Wp   = (const float*)d_in[15];
    const float* bp   = (const float*)d_in[16];
    float* out = (float*)d_out;

    float *g_h_p, *g_hn_p, *g_wba_p, *g_wbb_p;
    cudaGetSymbolAddress((void**)&g_h_p,   g_h);
    cudaGetSymbolAddress((void**)&g_hn_p,  g_hn);
    cudaGetSymbolAddress((void**)&g_wba_p, g_wba);
    cudaGetSymbolAddress((void**)&g_wbb_p, g_wbb);

    cudaFuncSetAttribute(gemm_qkvs_mma, cudaFuncAttributeMaxDynamicSharedMemorySize, MMASMEM);
    cudaFuncSetAttribute(gemm_proj_mma, cudaFuncAttributeMaxDynamicSharedMemorySize, PROJSMEM);

    // CSR build + weight split (once per call)
    csr_zero<<<(NN + 255) / 256, 256>>>();
    csr_count<<<(NE + 255) / 256, 256>>>(ei);
    csr_scan<<<1, 1024>>>();
    csr_fill<<<(NE + 255) / 256, 256>>>(ei);
    tsplit_qkvs<<<dim3(32, 4, LAYERS * 4), dim3(32, 8)>>>(Wq, Wk, Wv, Ws);
    tsplit_proj<<<dim3(4, 32, LAYERS), dim3(32, 8)>>>(Wp);
    weff_kernel<<<(LAYERS * HC + 255) / 256, 256>>>(Wb);

    inproj_kernel<<<(NN + 15) / 16, 128>>>(x, Win, b_in, g_h_p);

    float* h  = g_h_p;
    float* hn = g_hn_p;
    int mtiles   = (NN + 127) / 128;  // 157
    int mtiles64 = (NN + 63) / 64;    // 313

    for (int l = 0; l < LAYERS; l++) {
        gemm_qkvs_mma<<<dim3(8, mtiles), 256, MMASMEM>>>(
            bq + l * HC, bk + l * HC, bv + l * HC, bs + l * HC, l, NN);

        attn_fused<<<NN, 128>>>(g_wba_p + (size_t)l * HC, g_wbb_p + (size_t)l * HC,
                                lng + (size_t)l * HC, lnb + (size_t)l * HC);

        float* dst = (l == LAYERS - 1) ? out : hn;
        gemm_proj_mma<<<dim3(1, mtiles64), 256, PROJSMEM>>>(
            bp + (size_t)l * HID, h, dst, l, NN);
        if (l < LAYERS - 1) { float* t = h; h = hn; hn = t; }
    }
}

// round 16
// speedup vs baseline: 1.1297x; 1.1297x over previous
#include <cuda_runtime.h>
#include <cuda_bf16.h>
#include <cuda_fp16.h>
#include <math.h>
#include <stdint.h>

#define NN   20000
#define NE   160000
#define NPAD 20096
#define HID  128
#define HEADS 8
#define HC   1024
#define LAYERS 6

// ---------------- scratch (device globals; no allocation allowed) ----------
static __device__ float g_h  [NN * HID];
static __device__ float g_hn [NN * HID];
static __device__ __align__(16) __half g_hh[NPAD * HID];   // h in fp16 (qkvs A, 2-term)
static __device__ __align__(16) __half g_qh[NN * HC];      // q in fp16
static __device__ __align__(16) __half g_kh[NN * HC];      // k in fp16
static __device__ __align__(16) __half g_vh[NN * HC];      // v in fp16
static __device__ __align__(16) __half g_xrh[NN * HC];     // xr in fp16
static __device__ __align__(16) __half g_oh[NPAD * HC];    // attn out hi (fp16 split)
static __device__ __align__(16) __half g_ol[NPAD * HC];    // attn out lo
// CSR
static __device__ int g_deg   [NN];
static __device__ int g_rowptr[NN + 1];
static __device__ int g_cur   [NN];
static __device__ int g_esrc  [NE];
// split-fp16 weights: qkvs transposed [z=l*4+ws][n=1024][k=128], proj [l][n=128][k=1024]
static __device__ __align__(16) __half g_wA_hi[LAYERS * 4 * 1024 * 128];
static __device__ __align__(16) __half g_wA_lo[LAYERS * 4 * 1024 * 128];
static __device__ __align__(16) __half g_wP_hi[LAYERS * 128 * 1024];
static __device__ __align__(16) __half g_wP_lo[LAYERS * 128 * 1024];
// beta-gate effective weights: w_a = Wb1 + Wb3, w_b = Wb2 - Wb3
static __device__ float g_wba[LAYERS * HC];
static __device__ float g_wbb[LAYERS * HC];

// ==================== PTX helpers ============================================
__device__ __forceinline__ uint32_t smem_u32(const void* p) {
    uint32_t a;
    asm("{ .reg .u64 t; cvta.to.shared.u64 t, %1; cvt.u32.u64 %0, t; }" : "=r"(a) : "l"(p));
    return a;
}
__device__ __forceinline__ void ldsm4(uint32_t& r0, uint32_t& r1, uint32_t& r2, uint32_t& r3,
                                      uint32_t addr) {
    asm volatile("ldmatrix.sync.aligned.m8n8.x4.shared.b16 {%0,%1,%2,%3}, [%4];"
                 : "=r"(r0), "=r"(r1), "=r"(r2), "=r"(r3) : "r"(addr));
}
__device__ __forceinline__ void mma_f32(float* c, const uint32_t* a, uint32_t b0, uint32_t b1) {
    asm volatile("mma.sync.aligned.m16n8k16.row.col.f32.f16.f16.f32 "
                 "{%0,%1,%2,%3}, {%4,%5,%6,%7}, {%8,%9}, {%0,%1,%2,%3};"
                 : "+f"(c[0]), "+f"(c[1]), "+f"(c[2]), "+f"(c[3])
                 : "r"(a[0]), "r"(a[1]), "r"(a[2]), "r"(a[3]), "r"(b0), "r"(b1));
}
__device__ __forceinline__ void cp_async16(uint32_t dst, const void* src) {
    asm volatile("cp.async.cg.shared.global [%0], [%1], 16;" :: "r"(dst), "l"(src) : "memory");
}
#define CP_COMMIT() asm volatile("cp.async.commit_group;" ::: "memory")
#define CP_WAIT0()  asm volatile("cp.async.wait_group 0;" ::: "memory")

__device__ __forceinline__ uint32_t pack_h2(float x, float y) {
    __half2 t = __floats2half2_rn(x, y);
    return *(uint32_t*)&t;
}
// fp16 hi/lo split: hi = rn(x), lo = rn(x - hi); residual ~2^-22|x|
__device__ __forceinline__ void split2(float a, float b, uint32_t& hi, uint32_t& lo) {
    __half h0 = __float2half_rn(a), h1 = __float2half_rn(b);
    float l0 = a - __half2float(h0), l1 = b - __half2float(h1);
    __half2 th(h0, h1);
    hi = *(uint32_t*)&th;
    lo = pack_h2(l0, l1);
}
__device__ __forceinline__ void unpack8(uint4 u, float* f) {
    float2 a = __half22float2(*(__half2*)&u.x);
    float2 b = __half22float2(*(__half2*)&u.y);
    float2 c = __half22float2(*(__half2*)&u.z);
    float2 d = __half22float2(*(__half2*)&u.w);
    f[0]=a.x; f[1]=a.y; f[2]=b.x; f[3]=b.y; f[4]=c.x; f[5]=c.y; f[6]=d.x; f[7]=d.y;
}

// 512B-row tile (hi+lo): 32 chunks of 16B; hi chunks 0-15, lo 16-31
__device__ __forceinline__ uint32_t sw_off(int r, int chunk) {
    return (uint32_t)(r * 512 + ((chunk ^ (r & 7)) << 4));
}
// 256B-row tile (hi only): 16 chunks of 16B
__device__ __forceinline__ uint32_t sw64(int r, int chunk) {
    return (uint32_t)(r * 256 + ((chunk ^ (r & 7)) << 4));
}

// qkvs smem: A-hi 32KB (128 rows x 256B), B0/B1 64KB each (hi+lo)
#define QA_OFF  0
#define QB0_OFF 32768
#define QB1_OFF 98304
#define QSMEM   163840
// proj smem: A 32KB (64 rows x 512B hi+lo), B0/B1 64KB each
#define PA_OFF  0
#define PB0_OFF 32768
#define PB1_OFF 98304
#define PSMEM   163840

// ---------------- qkvs MMA mainloop, 128x128 tile, 2-term (Ah*Bh + Ah*Bl) ---
__device__ __forceinline__ void mma_k128_2t(uint32_t smA, uint32_t smB, int lane,
                                            int wm, int wn, float acc[2][8][4]) {
    int arow0 = wm * 32 + (lane & 15);
    int asel  = (lane >> 4) & 1;
    int brow0 = wn * 64 + (lane & 7) + ((lane >> 4) & 1) * 8;
    int bsel  = (lane >> 3) & 1;
    #pragma unroll
    for (int k16 = 0; k16 < 8; k16++) {
        int ch = 2 * k16;
        uint32_t ah[2][4];
        #pragma unroll
        for (int mf = 0; mf < 2; mf++) {
            int r = arow0 + mf * 16;
            uint32_t ad = smA + sw64(r, ch + asel);
            ldsm4(ah[mf][0], ah[mf][1], ah[mf][2], ah[mf][3], ad);
        }
        uint32_t bh_[8][2], bl_[8][2];
        #pragma unroll
        for (int p = 0; p < 4; p++) {
            int r = brow0 + p * 16;
            uint32_t bd = smB + sw_off(r, ch + bsel);
            ldsm4(bh_[2*p][0], bh_[2*p][1], bh_[2*p+1][0], bh_[2*p+1][1], bd);
            ldsm4(bl_[2*p][0], bl_[2*p][1], bl_[2*p+1][0], bl_[2*p+1][1], bd + 256);
        }
        #pragma unroll
        for (int mf = 0; mf < 2; mf++)
            #pragma unroll
            for (int nf = 0; nf < 8; nf++) {
                mma_f32(acc[mf][nf], ah[mf], bh_[nf][0], bh_[nf][1]);
                mma_f32(acc[mf][nf], ah[mf], bl_[nf][0], bl_[nf][1]);
            }
    }
}

// ---------------- proj MMA mainloop, 64x128 tile, 3-term --------------------
__device__ __forceinline__ void mma_k128_m64(uint32_t smA, uint32_t smB, int lane,
                                             int wm, int wn, float acc[2][4][4]) {
    int arow0 = wm * 32 + (lane & 15);
    int asel  = (lane >> 4) & 1;
    int brow0 = wn * 32 + (lane & 7) + ((lane >> 4) & 1) * 8;
    int bsel  = (lane >> 3) & 1;
    #pragma unroll
    for (int k16 = 0; k16 < 8; k16++) {
        int ch = 2 * k16;
        uint32_t ah[2][4], al[2][4];
        #pragma unroll
        for (int mf = 0; mf < 2; mf++) {
            int r = arow0 + mf * 16;
            uint32_t ad = smA + sw_off(r, ch + asel);
            ldsm4(ah[mf][0], ah[mf][1], ah[mf][2], ah[mf][3], ad);
            ldsm4(al[mf][0], al[mf][1], al[mf][2], al[mf][3], ad + 256);
        }
        uint32_t bh_[4][2], bl_[4][2];
        #pragma unroll
        for (int p = 0; p < 2; p++) {
            int r = brow0 + p * 16;
            uint32_t bd = smB + sw_off(r, ch + bsel);
            ldsm4(bh_[2*p][0], bh_[2*p][1], bh_[2*p+1][0], bh_[2*p+1][1], bd);
            ldsm4(bl_[2*p][0], bl_[2*p][1], bl_[2*p+1][0], bl_[2*p+1][1], bd + 256);
        }
        #pragma unroll
        for (int mf = 0; mf < 2; mf++)
            #pragma unroll
            for (int nf = 0; nf < 4; nf++) {
                mma_f32(acc[mf][nf], ah[mf], bh_[nf][0], bh_[nf][1]);
                mma_f32(acc[mf][nf], al[mf], bh_[nf][0], bh_[nf][1]);
                mma_f32(acc[mf][nf], ah[mf], bl_[nf][0], bl_[nf][1]);
            }
    }
}

// ---------------- qkvs GEMM: M128 tiles, 2-term, pure cp.async ---------------
// grid (8, 157): x = ws*2 + nhalf, y = m-tile(128). All outputs fp16.
__global__ __launch_bounds__(256, 1) void gemm_qkvs_mma(
        const float* __restrict__ bq, const float* __restrict__ bk,
        const float* __restrict__ bv, const float* __restrict__ bs,
        int l, int M) {
    extern __shared__ char sm[];
    int tid = threadIdx.x, wid = tid >> 5, lane = tid & 31;
    int ws = blockIdx.x >> 1, nh = blockIdx.x & 1;
    int m0 = blockIdx.y * 128;
    int z = l * 4 + ws;
    const float* bias = ws == 0 ? bq : ws == 1 ? bk : ws == 2 ? bv : bs;
    __half* Ch = ws == 0 ? g_qh : ws == 1 ? g_kh : ws == 2 ? g_vh : g_xrh;
    const uint4* bhp = (const uint4*)g_wA_hi + (size_t)z * 1024 * 16;
    const uint4* blp = (const uint4*)g_wA_lo + (size_t)z * 1024 * 16;
    uint32_t smb = smem_u32(sm);

    // prefetch A-hi and B tile 0, all async
    for (int i = tid; i < 2048; i += 256) {
        int r = i >> 4, c = i & 15;
        cp_async16(smb + QA_OFF + sw64(r, c), g_hh + (size_t)(m0 + r) * 128 + c * 8);
        int n0 = nh * 512;
        uint32_t ob = smb + QB0_OFF + sw_off(r, c);
        cp_async16(ob,       bhp + (size_t)(n0 + r) * 16 + c);
        cp_async16(ob + 256, blp + (size_t)(n0 + r) * 16 + c);
    }
    CP_COMMIT();
    CP_WAIT0();
    __syncthreads();

    int wm = wid >> 1, wn = wid & 1;
    for (int nt = 0; nt < 4; nt++) {
        int n0 = (nh * 4 + nt) * 128;
        if (nt < 3) {      // prefetch next B tile into the other buffer
            int n1 = n0 + 128;
            uint32_t boff = ((nt + 1) & 1) ? QB1_OFF : QB0_OFF;
            for (int i = tid; i < 2048; i += 256) {
                int r = i >> 4, c = i & 15;
                uint32_t oh = smb + boff + sw_off(r, c);
                cp_async16(oh,       bhp + (size_t)(n1 + r) * 16 + c);
                cp_async16(oh + 256, blp + (size_t)(n1 + r) * 16 + c);
            }
            CP_COMMIT();
        }
        float acc[2][8][4] = {};
        mma_k128_2t(smb + QA_OFF, smb + ((nt & 1) ? QB1_OFF : QB0_OFF),
                    lane, wm, wn, acc);

        int colb = n0 + wn * 64 + (lane & 3) * 2;
        #pragma unroll
        for (int mf = 0; mf < 2; mf++) {
            int r0 = m0 + wm * 32 + mf * 16 + (lane >> 2);
            #pragma unroll
            for (int nf = 0; nf < 8; nf++) {
                int col = colb + nf * 8;
                float2 bb = *(const float2*)(bias + col);
                if (r0 < M)
                    *(uint32_t*)(Ch + (size_t)r0 * HC + col) =
                        pack_h2(acc[mf][nf][0] + bb.x, acc[mf][nf][1] + bb.y);
                if (r0 + 8 < M)
                    *(uint32_t*)(Ch + (size_t)(r0 + 8) * HC + col) =
                        pack_h2(acc[mf][nf][2] + bb.x, acc[mf][nf][3] + bb.y);
            }
        }
        if (nt < 3) CP_WAIT0();
        __syncthreads();
    }
}

// ---------------- proj GEMM: M64 tiles (313 blocks), 3-term ------------------
// grid (1, 313). 8 warps = 2(m) x 4(n), each 32x32.
// Epilogue writes fp32 C (+resid+relu) AND fp16 h for next qkvs.
__global__ __launch_bounds__(256, 1) void gemm_proj_mma(
        const float* __restrict__ bias, const float* __restrict__ resid,
        float* __restrict__ C, int l, int M) {
    extern __shared__ char sm[];
    int tid = threadIdx.x, wid = tid >> 5, lane = tid & 31;
    int m0 = blockIdx.y * 64;
    const uint4* ahp = (const uint4*)g_oh + (size_t)m0 * 128;          // [row][128 u4]
    const uint4* alp = (const uint4*)g_ol + (size_t)m0 * 128;
    const uint4* bhp = (const uint4*)g_wP_hi + (size_t)l * 128 * 128;  // [n=128][128 u4]
    const uint4* blp = (const uint4*)g_wP_lo + (size_t)l * 128 * 128;
    uint32_t smb = smem_u32(sm);

    // prefetch A chunk 0 (64 rows, hi+lo) + B chunk 0 (128 rows)
    for (int i = tid; i < 1024; i += 256) {
        int r = i >> 4, c = i & 15;
        uint32_t oa = smb + PA_OFF + sw_off(r, c);
        cp_async16(oa,       ahp + (size_t)r * 128 + c);
        cp_async16(oa + 256, alp + (size_t)r * 128 + c);
    }
    for (int i = tid; i < 2048; i += 256) {
        int r = i >> 4, c = i & 15;
        uint32_t ob = smb + PB0_OFF + sw_off(r, c);
        cp_async16(ob,       bhp + (size_t)r * 128 + c);
        cp_async16(ob + 256, blp + (size_t)r * 128 + c);
    }
    CP_COMMIT();
    CP_WAIT0();
    __syncthreads();

    float acc[2][4][4] = {};
    int wm = wid >> 2, wn = wid & 3;

    for (int ck = 0; ck < 8; ck++) {
        if (ck < 7) {     // prefetch next B chunk (overlaps MMA)
            uint32_t boff = ((ck + 1) & 1) ? PB1_OFF : PB0_OFF;
            for (int i = tid; i < 2048; i += 256) {
                int r = i >> 4, c = i & 15;
                uint32_t oh = smb + boff + sw_off(r, c);
                cp_async16(oh,       bhp + (size_t)r * 128 + (ck + 1) * 16 + c);
                cp_async16(oh + 256, blp + (size_t)r * 128 + (ck + 1) * 16 + c);
            }
            CP_COMMIT();
        }
        mma_k128_m64(smb + PA_OFF, smb + ((ck & 1) ? PB1_OFF : PB0_OFF),
                     lane, wm, wn, acc);
        __syncthreads();
        if (ck < 7) {     // restage A for next chunk (pure async copy, 32KB)
            for (int i = tid; i < 1024; i += 256) {
                int r = i >> 4, c = i & 15;
                uint32_t oa = smb + PA_OFF + sw_off(r, c);
                cp_async16(oa,       ahp + (size_t)r * 128 + (ck + 1) * 16 + c);
                cp_async16(oa + 256, alp + (size_t)r * 128 + (ck + 1) * 16 + c);
            }
            CP_COMMIT();
            CP_WAIT0();
        }
        __syncthreads();
    }

    int colb = wn * 32 + (lane & 3) * 2;
    #pragma unroll
    for (int mf = 0; mf < 2; mf++) {
        int r0 = m0 + wm * 32 + mf * 16 + (lane >> 2);
        #pragma unroll
        for (int nf = 0; nf < 4; nf++) {
            int col = colb + nf * 8;
            float2 bb = *(const float2*)(bias + col);
            if (r0 < M) {
                float2 rr = *(const float2*)(resid + (size_t)r0 * HID + col);
                float2 o;
                o.x = fmaxf(acc[mf][nf][0] + bb.x + rr.x, 0.f);
                o.y = fmaxf(acc[mf][nf][1] + bb.y + rr.y, 0.f);
                *(float2*)(C + (size_t)r0 * HID + col) = o;
                *(uint32_t*)(g_hh + (size_t)r0 * HID + col) = pack_h2(o.x, o.y);
            }
            if (r0 + 8 < M) {
                float2 rr = *(const float2*)(resid + (size_t)(r0 + 8) * HID + col);
                float2 o;
                o.x = fmaxf(acc[mf][nf][2] + bb.x + rr.x, 0.f);
                o.y = fmaxf(acc[mf][nf][3] + bb.y + rr.y, 0.f);
                *(float2*)(C + (size_t)(r0 + 8) * HID + col) = o;
                *(uint32_t*)(g_hh + (size_t)(r0 + 8) * HID + col) = pack_h2(o.x, o.y);
            }
        }
    }
}

// ---------------- weight transpose + split (fp16 hi/lo) ----------------------
__global__ void tsplit_qkvs(const float* __restrict__ Wq, const float* __restrict__ Wk,
                            const float* __restrict__ Wv, const float* __restrict__ Ws) {
    __shared__ float t[32][33];
    int z = blockIdx.z, l = z >> 2, ws = z & 3;
    const float* W = (ws == 0 ? Wq : ws == 1 ? Wk : ws == 2 ? Wv : Ws) + (size_t)l * 128 * HC;
    __half* oh = g_wA_hi + (size_t)z * 1024 * 128;
    __half* ol = g_wA_lo + (size_t)z * 1024 * 128;
    int n0 = blockIdx.x * 32, k0 = blockIdx.y * 32;
    int tx = threadIdx.x, ty = threadIdx.y;
    #pragma unroll
    for (int i = 0; i < 4; i++)
        t[ty + 8 * i][tx] = W[(size_t)(k0 + ty + 8 * i) * HC + n0 + tx];
    __syncthreads();
    #pragma unroll
    for (int i = 0; i < 4; i++) {
        float v = t[tx][ty + 8 * i];
        __half h = __float2half_rn(v);
        size_t o = (size_t)(n0 + ty + 8 * i) * 128 + k0 + tx;
        oh[o] = h;
        ol[o] = __float2half_rn(v - __half2float(h));
    }
}
__global__ void tsplit_proj(const float* __restrict__ Wp) {
    __shared__ float t[32][33];
    int l = blockIdx.z;
    const float* W = Wp + (size_t)l * 1024 * 128;
    __half* oh = g_wP_hi + (size_t)l * 128 * 1024;
    __half* ol = g_wP_lo + (size_t)l * 128 * 1024;
    int n0 = blockIdx.x * 32, k0 = blockIdx.y * 32;
    int tx = threadIdx.x, ty = threadIdx.y;
    #pragma unroll
    for (int i = 0; i < 4; i++)
        t[ty + 8 * i][tx] = W[(size_t)(k0 + ty + 8 * i) * 128 + n0 + tx];
    __syncthreads();
    #pragma unroll
    for (int i = 0; i < 4; i++) {
        float v = t[tx][ty + 8 * i];
        __half h = __float2half_rn(v);
        size_t o = (size_t)(n0 + ty + 8 * i) * 1024 + k0 + tx;
        oh[o] = h;
        ol[o] = __float2half_rn(v - __half2float(h));
    }
}
// beta-gate effective weights
__global__ void weff_kernel(const float* __restrict__ Wb) {
    int i = blockIdx.x * blockDim.x + threadIdx.x;
    if (i < LAYERS * HC) {
        int l = i / HC, c = i % HC;
        const float* w = Wb + (size_t)l * 3 * HC;
        g_wba[i] = w[c] + w[2 * HC + c];
        g_wbb[i] = w[HC + c] - w[2 * HC + c];
    }
}

// ---------------- input projection: 16 nodes/block, Win cached in smem ------
__global__ __launch_bounds__(128) void inproj_kernel(
        const float* __restrict__ x, const float* __restrict__ Win,
        const float* __restrict__ b_in, float* __restrict__ h) {
    __shared__ float sw[15][128];
    __shared__ float sb[128];
    __shared__ float sx[16][16];
    int j = threadIdx.x;
    #pragma unroll
    for (int k = 0; k < 15; k++) sw[k][j] = Win[k * HID + j];
    sb[j] = b_in[j];
    int nb = blockIdx.x * 16;
    for (int i = j; i < 240; i += 128) {
        int ni = i / 15, ci = i % 15;
        int n = nb + ni;
        sx[ni][ci] = (n < NN) ? x[(size_t)n * 15 + ci] : 0.f;
    }
    __syncthreads();
    #pragma unroll 4
    for (int ni = 0; ni < 16; ni++) {
        int n = nb + ni;
        if (n >= NN) break;
        float acc = sb[j];
        #pragma unroll
        for (int k = 0; k < 15; k++) acc += sx[ni][k] * sw[k][j];
        h[(size_t)n * HID + j] = acc;
        g_hh[(size_t)n * HID + j] = __float2half_rn(acc);
    }
}

// ---------------- CSR build --------------------------------------------------
__global__ void csr_zero() {
    int i = blockIdx.x * blockDim.x + threadIdx.x;
    if (i < NN) g_deg[i] = 0;
}
__global__ void csr_count(const int* __restrict__ ei) {
    int e = blockIdx.x * blockDim.x + threadIdx.x;
    if (e < NE) atomicAdd(&g_deg[ei[NE + e]], 1);
}
__global__ __launch_bounds__(1024) void csr_scan() {
    __shared__ int wsum[32], wofs[32], s_tot;
    int t = threadIdx.x, lane = t & 31, w = t >> 5;
    int base = 0;
    for (int i0 = 0; i0 < NN; i0 += 1024) {
        int i = i0 + t;
        int v = (i < NN) ? g_deg[i] : 0;
        int s = v;
        #pragma unroll
        for (int o = 1; o < 32; o <<= 1) {
            int u = __shfl_up_sync(0xffffffffu, s, o);
            if (lane >= o) s += u;
        }
        if (lane == 31) wsum[w] = s;
        __syncthreads();
        if (w == 0) {
            int a = wsum[lane];
            int ss = a;
            #pragma unroll
            for (int o = 1; o < 32; o <<= 1) {
                int u = __shfl_up_sync(0xffffffffu, ss, o);
                if (lane >= o) ss += u;
            }
            wofs[lane] = ss - a;
            if (lane == 31) s_tot = ss;
        }
        __syncthreads();
        int excl = base + wofs[w] + (s - v);
        if (i < NN) { g_rowptr[i] = excl; g_cur[i] = excl; }
        base += s_tot;
        __syncthreads();
    }
    if (t == 0) g_rowptr[NN] = base;
}
__global__ void csr_fill(const int* __restrict__ ei) {
    int e = blockIdx.x * blockDim.x + threadIdx.x;
    if (e < NE) {
        int dst = ei[NE + e];
        int pos = atomicAdd(&g_cur[dst], 1);
        g_esrc[pos] = ei[e];
    }
}

// ---------------- fused attention + beta gate + LayerNorm -------------------
// block = 128 threads; thread t: head h = t>>4, owns 8 cols. No-max softmax,
// 2-way unrolled edge streams. Single-pass LN (Var = E[g^2] - mu^2).
__device__ __forceinline__ float breduce128(float v, float* red) {
    #pragma unroll
    for (int o = 16; o; o >>= 1) v += __shfl_xor_sync(0xffffffffu, v, o);
    if ((threadIdx.x & 31) == 0) red[threadIdx.x >> 5] = v;
    __syncthreads();
    float r = red[0] + red[1] + red[2] + red[3];
    __syncthreads();
    return r;
}
__device__ __forceinline__ float2 breduce128_2(float a, float b, float* red) {
    #pragma unroll
    for (int o = 16; o; o >>= 1) {
        a += __shfl_xor_sync(0xffffffffu, a, o);
        b += __shfl_xor_sync(0xffffffffu, b, o);
    }
    if ((threadIdx.x & 31) == 0) {
        red[(threadIdx.x >> 5) * 2]     = a;
        red[(threadIdx.x >> 5) * 2 + 1] = b;
    }
    __syncthreads();
    float2 r;
    r.x = red[0] + red[2] + red[4] + red[6];
    r.y = red[1] + red[3] + red[5] + red[7];
    __syncthreads();
    return r;
}

__global__ __launch_bounds__(128) void attn_fused(
        const float* __restrict__ wba, const float* __restrict__ wbb,
        const float* __restrict__ lng, const float* __restrict__ lnb) {
    int n = blockIdx.x;
    int t = threadIdx.x;
    int off = (t >> 4) * 128 + (t & 15) * 8;
    __shared__ float red[8];
    const float RSQ = 0.08838834764831845f;   // 1/sqrt(128)

    float q[8];
    unpack8(*(const uint4*)(g_qh + (size_t)n * HC + off), q);

    float acc0[8] = {}, acc1[8] = {};
    float d0 = 0.f, d1 = 0.f;

    int beg = g_rowptr[n], end = g_rowptr[n + 1];
    int p = beg;
    for (; p + 1 < end; p += 2) {
        int s0 = g_esrc[p], s1 = g_esrc[p + 1];
        uint4 ku0 = *(const uint4*)(g_kh + (size_t)s0 * HC + off);
        uint4 ku1 = *(const uint4*)(g_kh + (size_t)s1 * HC + off);
        uint4 vu0 = *(const uint4*)(g_vh + (size_t)s0 * HC + off);
        uint4 vu1 = *(const uint4*)(g_vh + (size_t)s1 * HC + off);
        float k0[8], k1[8], v0[8], v1[8];
        unpack8(ku0, k0); unpack8(ku1, k1);
        unpack8(vu0, v0); unpack8(vu1, v1);
        float dot0 = 0.f, dot1 = 0.f;
        #pragma unroll
        for (int i = 0; i < 8; i++) { dot0 += q[i] * k0[i]; dot1 += q[i] * k1[i]; }
        #pragma unroll
        for (int o = 8; o; o >>= 1) {
            dot0 += __shfl_xor_sync(0xffffffffu, dot0, o);
            dot1 += __shfl_xor_sync(0xffffffffu, dot1, o);
        }
        float pw0 = __expf(dot0 * RSQ);
        float pw1 = __expf(dot1 * RSQ);
        d0 += pw0; d1 += pw1;
        #pragma unroll
        for (int i = 0; i < 8; i++) {
            acc0[i] += pw0 * v0[i];
            acc1[i] += pw1 * v1[i];
        }
    }
    if (p < end) {
        int s0 = g_esrc[p];
        uint4 ku0 = *(const uint4*)(g_kh + (size_t)s0 * HC + off);
        uint4 vu0 = *(const uint4*)(g_vh + (size_t)s0 * HC + off);
        float k0[8], v0[8];
        unpack8(ku0, k0); unpack8(vu0, v0);
        float dot0 = 0.f;
        #pragma unroll
        for (int i = 0; i < 8; i++) dot0 += q[i] * k0[i];
        #pragma unroll
        for (int o = 8; o; o >>= 1) dot0 += __shfl_xor_sync(0xffffffffu, dot0, o);
        float pw0 = __expf(dot0 * RSQ);
        d0 += pw0;
        #pragma unroll
        for (int i = 0; i < 8; i++) acc0[i] += pw0 * v0[i];
    }

    float inv = 1.f / (d0 + d1 + 1e-16f);
    float outv[8];
    #pragma unroll
    for (int i = 0; i < 8; i++) outv[i] = (acc0[i] + acc1[i]) * inv;

    float xr[8];
    unpack8(*(const uint4*)(g_xrh + (size_t)n * HC + off), xr);
    float bsum = 0.f;
    #pragma unroll
    for (int i = 0; i < 8; i++)
        bsum += outv[i] * wba[off + i] + xr[i] * wbb[off + i];
    float tot = breduce128(bsum, red);
    float beta = 1.f / (1.f + __expf(-tot));

    float g[8], gsum = 0.f, g2sum = 0.f;
    #pragma unroll
    for (int i = 0; i < 8; i++) {
        g[i] = beta * xr[i] + (1.f - beta) * outv[i];
        gsum += g[i];
        g2sum += g[i] * g[i];
    }
    float2 ms = breduce128_2(gsum, g2sum, red);
    float mu  = ms.x * (1.f / HC);
    float var = ms.y * (1.f / HC) - mu * mu;
    float rstd = rsqrtf(var + 1e-5f);

    const float4* lg = (const float4*)(lng + off);
    const float4* lb = (const float4*)(lnb + off);
    float4 lg0 = lg[0], lg1 = lg[1], lb0 = lb[0], lb1 = lb[1];
    float gl[8] = {lg0.x, lg0.y, lg0.z, lg0.w, lg1.x, lg1.y, lg1.z, lg1.w};
    float bl[8] = {lb0.x, lb0.y, lb0.z, lb0.w, lb1.x, lb1.y, lb1.z, lb1.w};
    float o[8];
    #pragma unroll
    for (int i = 0; i < 8; i++) o[i] = (g[i] - mu) * rstd * gl[i] + bl[i];

    uint4 hu, lu;
    split2(o[0], o[1], hu.x, lu.x);
    split2(o[2], o[3], hu.y, lu.y);
    split2(o[4], o[5], hu.z, lu.z);
    split2(o[6], o[7], hu.w, lu.w);
    *(uint4*)(g_oh + (size_t)n * HC + off) = hu;
    *(uint4*)(g_ol + (size_t)n * HC + off) = lu;
}

// ---------------- launch -----------------------------------------------------
extern "C" void kernel_launch(void* const* d_in, const int* in_sizes, int n_in,
                              void* d_out, int out_size) {
    const float* x    = (const float*)d_in[0];
    const int*   ei   = (const int*)  d_in[1];
    const float* Win  = (const float*)d_in[2];
    const float* b_in = (const float*)d_in[3];
    const float* Wq   = (const float*)d_in[4];
    const float* bq   = (const float*)d_in[5];
    const float* Wk   = (const float*)d_in[6];
    const float* bk   = (const float*)d_in[7];
    const float* Wv   = (const float*)d_in[8];
    const float* bv   = (const float*)d_in[9];
    const float* Ws   = (const float*)d_in[10];
    const float* bs   = (const float*)d_in[11];
    const float* Wb   = (const float*)d_in[12];
    const float* lng  = (const float*)d_in[13];
    const float* lnb  = (const float*)d_in[14];
    const float* Wp   = (const float*)d_in[15];
    const float* bp   = (const float*)d_in[16];
    float* out = (float*)d_out;

    float *g_h_p, *g_hn_p, *g_wba_p, *g_wbb_p;
    cudaGetSymbolAddress((void**)&g_h_p,   g_h);
    cudaGetSymbolAddress((void**)&g_hn_p,  g_hn);
    cudaGetSymbolAddress((void**)&g_wba_p, g_wba);
    cudaGetSymbolAddress((void**)&g_wbb_p, g_wbb);

    cudaFuncSetAttribute(gemm_qkvs_mma, cudaFuncAttributeMaxDynamicSharedMemorySize, QSMEM);
    cudaFuncSetAttribute(gemm_proj_mma, cudaFuncAttributeMaxDynamicSharedMemorySize, PSMEM);

    // CSR build + weight split (once per call)
    csr_zero<<<(NN + 255) / 256, 256>>>();
    csr_count<<<(NE + 255) / 256, 256>>>(ei);
    csr_scan<<<1, 1024>>>();
    csr_fill<<<(NE + 255) / 256, 256>>>(ei);
    tsplit_qkvs<<<dim3(32, 4, LAYERS * 4), dim3(32, 8)>>>(Wq, Wk, Wv, Ws);
    tsplit_proj<<<dim3(4, 32, LAYERS), dim3(32, 8)>>>(Wp);
    weff_kernel<<<(LAYERS * HC + 255) / 256, 256>>>(Wb);

    inproj_kernel<<<(NN + 15) / 16, 128>>>(x, Win, b_in, g_h_p);

    float* h  = g_h_p;
    float* hn = g_hn_p;
    int mtiles   = (NN + 127) / 128;  // 157
    int mtiles64 = (NN + 63) / 64;    // 313

    for (int l = 0; l < LAYERS; l++) {
        gemm_qkvs_mma<<<dim3(8, mtiles), 256, QSMEM>>>(
            bq + l * HC, bk + l * HC, bv + l * HC, bs + l * HC, l, NN);

        attn_fused<<<NN, 128>>>(g_wba_p + (size_t)l * HC, g_wbb_p + (size_t)l * HC,
                                lng + (size_t)l * HC, lnb + (size_t)l * HC);

        float* dst = (l == LAYERS - 1) ? out : hn;
        gemm_proj_mma<<<dim3(1, mtiles64), 256, PSMEM>>>(
            bp + (size_t)l * HID, h, dst, l, NN);
        if (l < LAYERS - 1) { float* t = h; h = hn; hn = t; }
    }
}